// round 3
// baseline (speedup 1.0000x reference)
#include <cuda_runtime.h>
#include <cuda_bf16.h>

#define NRELS_MAX 64
#define RELPAD 19   // 19 coprime with 32 -> distinct rels hit distinct smem banks

__global__ __launch_bounds__(256, 5)
void alpha_model_kernel(const float* __restrict__ prnt,
                        const float* __restrict__ child,
                        const float* __restrict__ rel_mu,
                        const float* __restrict__ rel_sigma,
                        const float* __restrict__ eps,
                        const float* __restrict__ beta,
                        const int*   __restrict__ rels,
                        float* __restrict__ out,
                        int N, int n_rels)
{
    __shared__ float sh[NRELS_MAX * RELPAD];
    int n_fill = n_rels * 18;
    for (int k = threadIdx.x; k < n_fill; k += blockDim.x) {
        int r = k / 18, o = k - r * 18;
        sh[r * RELPAD + o] = (o < 9) ? rel_mu[r * 9 + o] : rel_sigma[r * 9 + o - 9];
    }
    __syncthreads();

    size_t e = (size_t)blockIdx.x * blockDim.x + threadIdx.x;
    size_t Ns = (size_t)N;
    if (e >= Ns) return;

    // ---- loads (1 edge per thread; warp-stride 12B / 36B, L1 coalesces sectors) ----
    float p0 = prnt[3*e],  p1 = prnt[3*e+1],  p2 = prnt[3*e+2];
    float c0 = child[3*e], c1 = child[3*e+1], c2 = child[3*e+2];
    float E0 = eps[9*e],   E1 = eps[9*e+1],   E2 = eps[9*e+2];
    float E3 = eps[9*e+3], E4 = eps[9*e+4],   E5 = eps[9*e+5];
    float E6 = eps[9*e+6], E7 = eps[9*e+7],   E8 = eps[9*e+8];
    float b  = beta[e];
    int   r  = rels[e];

    float csum = c0 + c1 + c2;
    float psum = p0 + p1 + p2;
    bool child_nz = (csum != 0.0f);
    bool prnt_z   = (psum == 0.0f);
    bool copym  = child_nz && prnt_z;
    bool alpham = child_nz && !prnt_z;

    const float* mb = sh + r * RELPAD;
    // y_i = sum_j (mu_ij + sigma_ij * eps_ij) * c_j
    float y0 = (mb[0] + mb[ 9]*E0)*c0 + (mb[1] + mb[10]*E1)*c1 + (mb[2] + mb[11]*E2)*c2;
    float y1 = (mb[3] + mb[12]*E3)*c0 + (mb[4] + mb[13]*E4)*c1 + (mb[5] + mb[14]*E5)*c2;
    float y2 = (mb[6] + mb[15]*E6)*c0 + (mb[7] + mb[16]*E7)*c1 + (mb[8] + mb[17]*E8)*c2;

    // softmax over 3
    float m  = fmaxf(y0, fmaxf(y1, y2));
    float q0 = __expf(y0 - m);
    float q1 = __expf(y1 - m);
    float q2 = __expf(y2 - m);
    float inv = __fdividef(1.0f, q0 + q1 + q2);
    float cp0 = q0 * inv, cp1 = q1 * inv, cp2 = q2 * inv;

    // scale: z = max(eps, p+cp); normalize; entropy
    float z0 = fmaxf(0.01f, p0 + cp0);
    float z1 = fmaxf(0.01f, p1 + cp1);
    float z2 = fmaxf(0.01f, p2 + cp2);
    float invZ = __fdividef(1.0f, z0 + z1 + z2);
    float zn0 = z0 * invZ, zn1 = z1 * invZ, zn2 = z2 * invZ;
    float H = -(zn0 * __logf(zn0) + zn1 * __logf(zn1) + zn2 * __logf(zn2));

    // cosine similarity (cp from softmax always has nonzero norm)
    float dot = p0*cp0 + p1*cp1 + p2*cp2;
    float sqp = p0*p0 + p1*p1 + p2*p2;
    float sqc = cp0*cp0 + cp1*cp1 + cp2*cp2;
    float cosv = (sqp == 0.0f) ? 0.0f : dot * rsqrtf(sqp) * rsqrtf(sqc);
    cosv = fmaxf(0.01f, cosv);
    float s = __fdividef(42.0f * cosv, H);

    float ob = 1.0f - b;
    float a0 = (ob*p0 + b*cp0) * s;
    float a1 = (ob*p1 + b*cp1) * s;
    float a2 = (ob*p2 + b*cp2) * s;

    // ---- streaming stores ----
    __stcs(out + e,              copym  ? 1.0f : 0.0f);
    __stcs(out + Ns + 3*e + 0,   copym  ? cp0  : 0.0f);
    __stcs(out + Ns + 3*e + 1,   copym  ? cp1  : 0.0f);
    __stcs(out + Ns + 3*e + 2,   copym  ? cp2  : 0.0f);
    __stcs(out + 4*Ns + e,       alpham ? 1.0f : 0.0f);
    __stcs(out + 5*Ns + 3*e + 0, alpham ? a0   : 0.0f);
    __stcs(out + 5*Ns + 3*e + 1, alpham ? a1   : 0.0f);
    __stcs(out + 5*Ns + 3*e + 2, alpham ? a2   : 0.0f);
}

extern "C" void kernel_launch(void* const* d_in, const int* in_sizes, int n_in,
                              void* d_out, int out_size) {
    // metadata order: prnt_probs, child_probs, rel_mu, rel_sigma, eps_M, beta, rels
    const float* prnt      = (const float*)d_in[0];
    const float* child     = (const float*)d_in[1];
    const float* rel_mu    = (const float*)d_in[2];
    const float* rel_sigma = (const float*)d_in[3];
    const float* eps       = (const float*)d_in[4];
    const float* beta      = (const float*)d_in[5];
    const int*   rels      = (const int*)d_in[6];

    int N = in_sizes[5];                 // beta is [N]
    int n_rels = in_sizes[2] / 9;        // rel_mu is [n_rels, 3, 3]
    if (n_rels > NRELS_MAX) n_rels = NRELS_MAX;

    int blocks = (N + 255) / 256;

    alpha_model_kernel<<<blocks, 256>>>(prnt, child, rel_mu, rel_sigma, eps,
                                        beta, rels, (float*)d_out, N, n_rels);
}

// round 5
// speedup vs baseline: 1.0279x; 1.0279x over previous
#include <cuda_runtime.h>
#include <cuda_bf16.h>

#define NRELS_MAX 64
#define RELPAD 19   // 19 coprime with 32 -> distinct rels hit distinct smem banks

// Per-edge computation.
//  out8: {copy_mask, cp0, cp1, cp2, alpha_mask, a0, a1, a2}
__device__ __forceinline__ void compute_edge(
    float p0, float p1, float p2,
    float c0, float c1, float c2,
    const float* __restrict__ E,
    int r, float b, const float* __restrict__ sh,
    float* __restrict__ out8)
{
    float csum = c0 + c1 + c2;
    float psum = p0 + p1 + p2;
    bool child_nz = (csum != 0.0f);
    bool prnt_z   = (psum == 0.0f);
    bool copym  = child_nz && prnt_z;
    bool alpham = child_nz && !prnt_z;

    const float* mb = sh + r * RELPAD;
    // y_i = sum_j (mu_ij + sigma_ij * eps_ij) * c_j
    float y0 = (mb[0] + mb[ 9]*E[0])*c0 + (mb[1] + mb[10]*E[1])*c1 + (mb[2] + mb[11]*E[2])*c2;
    float y1 = (mb[3] + mb[12]*E[3])*c0 + (mb[4] + mb[13]*E[4])*c1 + (mb[5] + mb[14]*E[5])*c2;
    float y2 = (mb[6] + mb[15]*E[6])*c0 + (mb[7] + mb[16]*E[7])*c1 + (mb[8] + mb[17]*E[8])*c2;

    // softmax over 3
    float m  = fmaxf(y0, fmaxf(y1, y2));
    float q0 = __expf(y0 - m);
    float q1 = __expf(y1 - m);
    float q2 = __expf(y2 - m);
    float inv = __fdividef(1.0f, q0 + q1 + q2);
    float cp0 = q0 * inv, cp1 = q1 * inv, cp2 = q2 * inv;

    // scale: z = max(eps, p+cp); normalize; entropy
    float z0 = fmaxf(0.01f, p0 + cp0);
    float z1 = fmaxf(0.01f, p1 + cp1);
    float z2 = fmaxf(0.01f, p2 + cp2);
    float invZ = __fdividef(1.0f, z0 + z1 + z2);
    float zn0 = z0 * invZ, zn1 = z1 * invZ, zn2 = z2 * invZ;
    float H = -(zn0 * __logf(zn0) + zn1 * __logf(zn1) + zn2 * __logf(zn2));

    // cosine similarity (cp from softmax always has nonzero norm)
    float dot = p0*cp0 + p1*cp1 + p2*cp2;
    float sqp = p0*p0 + p1*p1 + p2*p2;
    float sqc = cp0*cp0 + cp1*cp1 + cp2*cp2;
    float cosv = (sqp == 0.0f) ? 0.0f : dot * rsqrtf(sqp) * rsqrtf(sqc);
    cosv = fmaxf(0.01f, cosv);
    float s = __fdividef(42.0f * cosv, H);

    float ob = 1.0f - b;
    float a0 = (ob*p0 + b*cp0) * s;
    float a1 = (ob*p1 + b*cp1) * s;
    float a2 = (ob*p2 + b*cp2) * s;

    out8[0] = copym  ? 1.0f : 0.0f;
    out8[1] = copym  ? cp0  : 0.0f;
    out8[2] = copym  ? cp1  : 0.0f;
    out8[3] = copym  ? cp2  : 0.0f;
    out8[4] = alpham ? 1.0f : 0.0f;
    out8[5] = alpham ? a0   : 0.0f;
    out8[6] = alpham ? a1   : 0.0f;
    out8[7] = alpham ? a2   : 0.0f;
}

__global__ __launch_bounds__(256, 5)
void alpha_model_kernel(const float* __restrict__ prnt,
                        const float* __restrict__ child,
                        const float* __restrict__ rel_mu,
                        const float* __restrict__ rel_sigma,
                        const float* __restrict__ eps,
                        const float* __restrict__ beta,
                        const int*   __restrict__ rels,
                        float* __restrict__ out,
                        int N, int n_rels)
{
    __shared__ float sh[NRELS_MAX * RELPAD];
    int n_fill = n_rels * 18;
    for (int k = threadIdx.x; k < n_fill; k += blockDim.x) {
        int r = k / 18, o = k - r * 18;
        sh[r * RELPAD + o] = (o < 9) ? rel_mu[r * 9 + o] : rel_sigma[r * 9 + o - 9];
    }
    __syncthreads();

    int t = blockIdx.x * blockDim.x + threadIdx.x;
    size_t Ns = (size_t)N;
    size_t e0 = (size_t)t * 2;
    if (e0 >= Ns) return;

    if (e0 + 1 < Ns && (N & 1) == 0) {
        // ---- vectorized path: 2 edges, all 64-bit streaming loads ----
        float pe[6], ce[6], ee[18];
        {
            const float2* p2 = reinterpret_cast<const float2*>(prnt) + (size_t)3 * t;
            const float2* c2 = reinterpret_cast<const float2*>(child) + (size_t)3 * t;
            const float2* e2 = reinterpret_cast<const float2*>(eps)   + (size_t)9 * t;
#pragma unroll
            for (int i = 0; i < 3; i++) {
                float2 v = __ldcs(p2 + i);
                pe[2*i] = v.x; pe[2*i+1] = v.y;
            }
#pragma unroll
            for (int i = 0; i < 3; i++) {
                float2 v = __ldcs(c2 + i);
                ce[2*i] = v.x; ce[2*i+1] = v.y;
            }
#pragma unroll
            for (int i = 0; i < 9; i++) {
                float2 v = __ldcs(e2 + i);
                ee[2*i] = v.x; ee[2*i+1] = v.y;
            }
        }
        float2 bv = __ldcs(reinterpret_cast<const float2*>(beta) + t);
        int2   rv = __ldcs(reinterpret_cast<const int2*>(rels) + t);

        float o8[16];
        compute_edge(pe[0], pe[1], pe[2], ce[0], ce[1], ce[2],
                     ee,     rv.x, bv.x, sh, o8);
        compute_edge(pe[3], pe[4], pe[5], ce[3], ce[4], ce[5],
                     ee + 9, rv.y, bv.y, sh, o8 + 8);

        // ---- 64-bit streaming stores, fully coalesced ----
        float2* outCM = reinterpret_cast<float2*>(out);
        float2* outCP = reinterpret_cast<float2*>(out + Ns);
        float2* outAM = reinterpret_cast<float2*>(out + 4 * Ns);
        float2* outAL = reinterpret_cast<float2*>(out + 5 * Ns);

        __stcs(outCM + t, make_float2(o8[0], o8[8]));
        __stcs(outAM + t, make_float2(o8[4], o8[12]));

        size_t b3 = (size_t)3 * t;
        __stcs(outCP + b3 + 0, make_float2(o8[1],  o8[2]));
        __stcs(outCP + b3 + 1, make_float2(o8[3],  o8[9]));
        __stcs(outCP + b3 + 2, make_float2(o8[10], o8[11]));
        __stcs(outAL + b3 + 0, make_float2(o8[5],  o8[6]));
        __stcs(outAL + b3 + 1, make_float2(o8[7],  o8[13]));
        __stcs(outAL + b3 + 2, make_float2(o8[14], o8[15]));
    } else {
        // ---- scalar tail ----
        for (size_t e = e0; e < Ns; e++) {
            float E[9];
#pragma unroll
            for (int i = 0; i < 9; i++) E[i] = eps[e * 9 + i];
            float o8[8];
            compute_edge(prnt[e*3], prnt[e*3+1], prnt[e*3+2],
                         child[e*3], child[e*3+1], child[e*3+2],
                         E, rels[e], beta[e], sh, o8);
            out[e]              = o8[0];
            out[Ns + 3*e + 0]   = o8[1];
            out[Ns + 3*e + 1]   = o8[2];
            out[Ns + 3*e + 2]   = o8[3];
            out[4*Ns + e]       = o8[4];
            out[5*Ns + 3*e + 0] = o8[5];
            out[5*Ns + 3*e + 1] = o8[6];
            out[5*Ns + 3*e + 2] = o8[7];
        }
    }
}

extern "C" void kernel_launch(void* const* d_in, const int* in_sizes, int n_in,
                              void* d_out, int out_size) {
    // metadata order: prnt_probs, child_probs, rel_mu, rel_sigma, eps_M, beta, rels
    const float* prnt      = (const float*)d_in[0];
    const float* child     = (const float*)d_in[1];
    const float* rel_mu    = (const float*)d_in[2];
    const float* rel_sigma = (const float*)d_in[3];
    const float* eps       = (const float*)d_in[4];
    const float* beta      = (const float*)d_in[5];
    const int*   rels      = (const int*)d_in[6];

    int N = in_sizes[5];                 // beta is [N]
    int n_rels = in_sizes[2] / 9;        // rel_mu is [n_rels, 3, 3]
    if (n_rels > NRELS_MAX) n_rels = NRELS_MAX;

    int nt = (N + 1) / 2;                // 2 edges per thread
    int blocks = (nt + 255) / 256;

    alpha_model_kernel<<<blocks, 256>>>(prnt, child, rel_mu, rel_sigma, eps,
                                        beta, rels, (float*)d_out, N, n_rels);
}